// round 9
// baseline (speedup 1.0000x reference)
#include <cuda_runtime.h>
#include <cuda_fp16.h>
#include <math.h>

#define NN 30000
#define EE 480000
#define EP 510000
#define LL 6
#define GG 128
#define FULL 0xffffffffu

typedef unsigned long long ull;

// ---------------- scratch (static device globals) ----------------
__device__ __align__(16) float  d_h  [NN*100];
__device__ __align__(16) float  d_hx [NN*400];      // fp32 hx (for scores)
__device__ __align__(16) __half d_hxh[NN*416];      // fp16 hx, heads padded to 104 (for gather)
__device__ __align__(16) float  d_es [LL*(size_t)EE*4];
__device__ __align__(16) float  d_si [NN*4];
__device__ __align__(16) float  d_sj [NN*4];
__device__ __align__(16) float  d_weff[LL*400];     // [l][d][h]
__device__ __align__(16) float  d_Wt [LL*40000];    // W transposed: [l][d][j]
__device__ int d_deg[NN];
__device__ int d_rowptr[NN+1];
__device__ int d_cursor[NN];
__device__ int d_csr_src[EP];
__device__ int d_csr_eid[EP];

// ---------------- f32x2 helpers ----------------
__device__ __forceinline__ ull fma2(ull a, ull b, ull c){
    ull r; asm("fma.rn.f32x2 %0, %1, %2, %3;" : "=l"(r) : "l"(a), "l"(b), "l"(c)); return r;
}
__device__ __forceinline__ ull pack2(float lo, float hi){
    ull r; asm("mov.b64 %0, {%1, %2};" : "=l"(r) : "f"(lo), "f"(hi)); return r;
}
__device__ __forceinline__ void unpack2(ull v, float &lo, float &hi){
    asm("mov.b64 {%0, %1}, %2;" : "=f"(lo), "=f"(hi) : "l"(v));
}

// ---------------- precompute ----------------
__global__ void k_zero_deg(){
    int i = blockIdx.x*blockDim.x + threadIdx.x;
    if (i < NN) d_deg[i] = 0;
}

__global__ void k_zpad(){
    int i = blockIdx.x*blockDim.x + threadIdx.x;
    if (i >= NN*16) return;
    int n = i/16, k = i%16, h = k/4, p = k%4;
    d_hxh[(size_t)n*416 + h*104 + 100 + p] = __float2half(0.f);
}

// w_eff[l][d][h] = sum_p a[l][h][100+p] * We[l][h*100+p][d]
__global__ void k_weff(const float* __restrict__ a, const float* __restrict__ We){
    int g = blockIdx.x*blockDim.x + threadIdx.x;
    if (g >= LL*400) return;
    int l = g/400, r = g%400, h = r/100, d = r%100;
    const float* ap = a  + l*800 + h*200 + 100;
    const float* wp = We + l*40000 + (h*100)*100 + d;
    float s = 0.f;
    #pragma unroll 4
    for (int p = 0; p < 100; p++) s = fmaf(ap[p], wp[p*100], s);
    d_weff[l*400 + d*4 + h] = s;
}

// Wt[l][d][j] = W[l][j][d]
__global__ void k_wt(const float* __restrict__ W){
    int i = blockIdx.x*blockDim.x + threadIdx.x;
    if (i >= LL*40000) return;
    int l = i/40000, r = i%40000, d = r/400, j = r%400;
    d_Wt[i] = W[l*40000 + j*100 + d];
}

// es[l][e][h]: 64 edges per block, 128 threads (2 per edge, 3 layers each)
__global__ void __launch_bounds__(128) k_es(const float* __restrict__ ea){
    __shared__ __align__(16) float sw[LL*400];
    __shared__ float rows[64*101];
    int tid = threadIdx.x;
    for (int i = tid; i < LL*400; i += 128) sw[i] = d_weff[i];
    int e0 = blockIdx.x*64;
    for (int i = tid; i < 64*100; i += 128){
        int el = i/100, d = i%100;
        int e = e0 + el;
        rows[el*101 + d] = (e < EE) ? ea[(size_t)e*100 + d] : 0.f;
    }
    __syncthreads();
    int el = tid & 63, half = tid >> 6;
    int e = e0 + el;
    if (e >= EE) return;
    const float* rp = rows + el*101;
    for (int l = half*3; l < half*3 + 3; l++){
        const float4* wl = (const float4*)(sw + l*400);
        float a0=0.f, a1=0.f, a2=0.f, a3=0.f;
        #pragma unroll 4
        for (int d = 0; d < 100; d++){
            float v = rp[d];
            float4 wv = wl[d];
            a0 = fmaf(v, wv.x, a0);
            a1 = fmaf(v, wv.y, a1);
            a2 = fmaf(v, wv.z, a2);
            a3 = fmaf(v, wv.w, a3);
        }
        *(float4*)(d_es + ((size_t)l*EE + e)*4) = make_float4(a0,a1,a2,a3);
    }
}

__global__ void k_h0(const int* __restrict__ x, const float* __restrict__ emb){
    int i = blockIdx.x*blockDim.x + threadIdx.x;
    if (i >= NN*25) return;
    int n = i/25, q = i%25;
    int atom = x[n];
    *(float4*)(d_h + n*100 + q*4) = *(const float4*)(emb + atom*100 + q*4);
}

// ---------------- CSR build ----------------
__global__ void k_hist(const int* __restrict__ ei){
    int e = blockIdx.x*blockDim.x + threadIdx.x;
    if (e >= EP) return;
    int dst = (e < EE) ? ei[EE + e] : (e - EE);
    atomicAdd(&d_deg[dst], 1);
}

__global__ void k_scan(){
    __shared__ int sh[1024];
    const int CH = 30;
    int t = threadIdx.x;
    int base = t*CH;
    int s = 0;
    for (int i = 0; i < CH; i++){ int idx = base+i; if (idx < NN) s += d_deg[idx]; }
    sh[t] = s; __syncthreads();
    for (int off = 1; off < 1024; off <<= 1){
        int v = (t >= off) ? sh[t-off] : 0;
        __syncthreads();
        sh[t] += v;
        __syncthreads();
    }
    int run = sh[t] - s;
    for (int i = 0; i < CH; i++){
        int idx = base+i;
        if (idx < NN){ d_rowptr[idx] = run; d_cursor[idx] = run; run += d_deg[idx]; }
    }
    if (t == 1023) d_rowptr[NN] = sh[1023];
}

__global__ void k_scatter(const int* __restrict__ ei){
    int e = blockIdx.x*blockDim.x + threadIdx.x;
    if (e >= EP) return;
    int dst, src, eid;
    if (e < EE){ dst = ei[EE+e]; src = ei[e]; eid = e; }
    else       { dst = e - EE;   src = dst;   eid = -1; }
    int pos = atomicAdd(&d_cursor[dst], 1);
    d_csr_src[pos] = src;
    d_csr_eid[pos] = eid;
}

// ---------------- per-layer GEMM ----------------
__global__ void __launch_bounds__(256,2) k_gemm(int l){
    __shared__ float hs[100][34];
    int tid = threadIdx.x;
    int node0 = blockIdx.x*32;
    const float* Wtl = d_Wt + l*40000;
    for (int i = tid; i < 3200; i += 256){
        int nl = i/100, d = i%100;
        int n = node0 + nl;
        hs[d][nl] = (n < NN) ? d_h[n*100 + d] : 0.f;
    }
    __syncthreads();
    int j0 = tid;
    bool has1 = (tid + 256) < 400;
    ull acc0[16], acc1[16];
    #pragma unroll
    for (int k = 0; k < 16; k++){ acc0[k] = 0ull; acc1[k] = 0ull; }
    for (int d = 0; d < 100; d++){
        float a0 = __ldg(Wtl + d*400 + j0);
        float a1 = has1 ? __ldg(Wtl + d*400 + j0 + 256) : 0.f;
        ull w0 = pack2(a0, a0), w1 = pack2(a1, a1);
        const ull* hrow = (const ull*)(&hs[d][0]);
        #pragma unroll
        for (int k = 0; k < 16; k++){
            ull hv = hrow[k];
            acc0[k] = fma2(hv, w0, acc0[k]);
            acc1[k] = fma2(hv, w1, acc1[k]);
        }
    }
    int mj0 = (j0/100)*104 + j0%100;
    int mj1 = ((j0+256)/100)*104 + (j0+256)%100;
    #pragma unroll
    for (int k = 0; k < 16; k++){
        int n0 = node0 + 2*k;
        float x0, x1; unpack2(acc0[k], x0, x1);
        if (n0 < NN){
            d_hx[(size_t)n0*400 + j0] = x0;
            d_hxh[(size_t)n0*416 + mj0] = __float2half_rn(x0);
        }
        if (n0+1 < NN){
            d_hx[(size_t)(n0+1)*400 + j0] = x1;
            d_hxh[(size_t)(n0+1)*416 + mj0] = __float2half_rn(x1);
        }
        if (has1){
            float y0, y1; unpack2(acc1[k], y0, y1);
            if (n0 < NN){
                d_hx[(size_t)n0*400 + j0 + 256] = y0;
                d_hxh[(size_t)n0*416 + mj1] = __float2half_rn(y0);
            }
            if (n0+1 < NN){
                d_hx[(size_t)(n0+1)*400 + j0 + 256] = y1;
                d_hxh[(size_t)(n0+1)*416 + mj1] = __float2half_rn(y1);
            }
        }
    }
}

// ---------------- scores: warp per node ----------------
__global__ void __launch_bounds__(256) k_score(const float* __restrict__ a, int l){
    __shared__ __align__(16) float sa[800];
    int tid = threadIdx.x;
    for (int i = tid; i < 800; i += 256) sa[i] = a[l*800 + i];
    __syncthreads();
    int lane = tid & 31, w = tid >> 5;
    int n = blockIdx.x*8 + w;
    if (n >= NN) return;
    const float4* hp = (const float4*)(d_hx + (size_t)n*400);
    float s0=0,s1=0,s2=0,s3=0, t0=0,t1=0,t2=0,t3=0;
    #pragma unroll
    for (int c = 0; c < 4; c++){
        int q = lane + c*32;
        if (q >= 100) break;
        float4 x = hp[q];
        int h = q/25, p4 = q%25;
        const float4* ab = (const float4*)(sa + h*200);
        float4 A = ab[p4], J = ab[25 + p4];
        float di = x.x*A.x + x.y*A.y + x.z*A.z + x.w*A.w;
        float dj = x.x*J.x + x.y*J.y + x.z*J.z + x.w*J.w;
        if      (h == 0){ s0 += di; t0 += dj; }
        else if (h == 1){ s1 += di; t1 += dj; }
        else if (h == 2){ s2 += di; t2 += dj; }
        else            { s3 += di; t3 += dj; }
    }
    #pragma unroll
    for (int off = 16; off; off >>= 1){
        s0 += __shfl_xor_sync(FULL, s0, off); s1 += __shfl_xor_sync(FULL, s1, off);
        s2 += __shfl_xor_sync(FULL, s2, off); s3 += __shfl_xor_sync(FULL, s3, off);
        t0 += __shfl_xor_sync(FULL, t0, off); t1 += __shfl_xor_sync(FULL, t1, off);
        t2 += __shfl_xor_sync(FULL, t2, off); t3 += __shfl_xor_sync(FULL, t3, off);
    }
    if (lane < 4){
        float vi = lane==0?s0 : lane==1?s1 : lane==2?s2 : s3;
        float vj = lane==0?t0 : lane==1?t1 : lane==2?t2 : t3;
        d_si[n*4 + lane] = vi;
        d_sj[n*4 + lane] = vj;
    }
}

// ---------------- node kernel: warp per node, online softmax + depth-2 pipelined gather ----------------
__global__ void __launch_bounds__(256) k_node(int l, const float* __restrict__ lng,
                                              const float* __restrict__ lnb){
    __shared__ float stage[8][416];
    int lane = threadIdx.x & 31, w = threadIdx.x >> 5;
    int n = blockIdx.x*8 + w;
    if (n >= NN) return;
    int rs = d_rowptr[n], re = d_rowptr[n+1];
    float4 si = *(const float4*)(d_si + n*4);
    int h0 = lane/13;                 // 0..2
    int h1 = (lane+32)/13;            // 2..3
    bool hasQ1 = lane < 20;

    float m0=-1e30f, m1=-1e30f, m2=-1e30f, m3=-1e30f;
    float den0=0.f, den1=0.f, den2=0.f, den3=0.f;
    float acc0[8], acc1[8];
    #pragma unroll
    for (int k = 0; k < 8; k++){ acc0[k] = 0.f; acc1[k] = 0.f; }

    for (int b = rs; b < re; b += 32){
        int idx = b + lane; bool ok = idx < re;
        int s   = ok ? d_csr_src[idx] : 0;
        int eid = ok ? d_csr_eid[idx] : -1;
        float4 sj = ok ? *(const float4*)(d_sj + s*4) : make_float4(0,0,0,0);
        float4 e4 = (eid >= 0) ? *(const float4*)(d_es + ((size_t)l*EE + eid)*4)
                               : make_float4(0,0,0,0);
        float v0 = si.x + sj.x + e4.x; v0 = v0 > 0.f ? v0 : 0.2f*v0; if(!ok) v0 = -1e30f;
        float v1 = si.y + sj.y + e4.y; v1 = v1 > 0.f ? v1 : 0.2f*v1; if(!ok) v1 = -1e30f;
        float v2 = si.z + sj.z + e4.z; v2 = v2 > 0.f ? v2 : 0.2f*v2; if(!ok) v2 = -1e30f;
        float v3 = si.w + sj.w + e4.w; v3 = v3 > 0.f ? v3 : 0.2f*v3; if(!ok) v3 = -1e30f;

        // block max per head
        float bm0 = v0, bm1 = v1, bm2 = v2, bm3 = v3;
        #pragma unroll
        for (int off = 16; off; off >>= 1){
            bm0 = fmaxf(bm0, __shfl_xor_sync(FULL, bm0, off));
            bm1 = fmaxf(bm1, __shfl_xor_sync(FULL, bm1, off));
            bm2 = fmaxf(bm2, __shfl_xor_sync(FULL, bm2, off));
            bm3 = fmaxf(bm3, __shfl_xor_sync(FULL, bm3, off));
        }
        float nm0 = fmaxf(m0, bm0), nm1 = fmaxf(m1, bm1);
        float nm2 = fmaxf(m2, bm2), nm3 = fmaxf(m3, bm3);
        float f0 = __expf(m0 - nm0), f1 = __expf(m1 - nm1);
        float f2 = __expf(m2 - nm2), f3 = __expf(m3 - nm3);
        m0 = nm0; m1 = nm1; m2 = nm2; m3 = nm3;
        den0 *= f0; den1 *= f1; den2 *= f2; den3 *= f3;
        float fa = (h0==0) ? f0 : (h0==1) ? f1 : f2;
        float fb = (h1==2) ? f2 : f3;
        #pragma unroll
        for (int k = 0; k < 8; k++){ acc0[k] *= fa; acc1[k] *= fb; }

        float e0 = __expf(v0 - nm0);
        float e1 = __expf(v1 - nm1);
        float e2 = __expf(v2 - nm2);
        float e3 = __expf(v3 - nm3);
        den0 += e0; den1 += e1; den2 += e2; den3 += e3;

        int cnt = min(32, re - b);
        // prefetch j = 0
        int   ssc = __shfl_sync(FULL, s, 0);
        float w0c = __shfl_sync(FULL, e0, 0);
        float w1c = __shfl_sync(FULL, e1, 0);
        float w2c = __shfl_sync(FULL, e2, 0);
        float w3c = __shfl_sync(FULL, e3, 0);
        float wac = (h0==0) ? w0c : (h0==1) ? w1c : w2c;
        float wbc = (h1==2) ? w2c : w3c;
        const uint4* bpc = (const uint4*)(d_hxh + (size_t)ssc*416);
        uint4 Ac = __ldg(bpc + lane);
        uint4 Bc = hasQ1 ? __ldg(bpc + 32 + lane) : make_uint4(0,0,0,0);
        uint4 An = Ac, Bn = Bc;
        float wan = 0.f, wbn = 0.f;
        for (int j = 0; j < cnt; j++){
            if (j + 1 < cnt){
                int   ssn = __shfl_sync(FULL, s,  j+1);
                float w0n = __shfl_sync(FULL, e0, j+1);
                float w1n = __shfl_sync(FULL, e1, j+1);
                float w2n = __shfl_sync(FULL, e2, j+1);
                float w3n = __shfl_sync(FULL, e3, j+1);
                wan = (h0==0) ? w0n : (h0==1) ? w1n : w2n;
                wbn = (h1==2) ? w2n : w3n;
                const uint4* bpn = (const uint4*)(d_hxh + (size_t)ssn*416);
                An = __ldg(bpn + lane);
                if (hasQ1) Bn = __ldg(bpn + 32 + lane);
            }
            float2 f;
            f = __half22float2(*(__half2*)&Ac.x); acc0[0] = fmaf(wac, f.x, acc0[0]); acc0[1] = fmaf(wac, f.y, acc0[1]);
            f = __half22float2(*(__half2*)&Ac.y); acc0[2] = fmaf(wac, f.x, acc0[2]); acc0[3] = fmaf(wac, f.y, acc0[3]);
            f = __half22float2(*(__half2*)&Ac.z); acc0[4] = fmaf(wac, f.x, acc0[4]); acc0[5] = fmaf(wac, f.y, acc0[5]);
            f = __half22float2(*(__half2*)&Ac.w); acc0[6] = fmaf(wac, f.x, acc0[6]); acc0[7] = fmaf(wac, f.y, acc0[7]);
            if (hasQ1){
                f = __half22float2(*(__half2*)&Bc.x); acc1[0] = fmaf(wbc, f.x, acc1[0]); acc1[1] = fmaf(wbc, f.y, acc1[1]);
                f = __half22float2(*(__half2*)&Bc.y); acc1[2] = fmaf(wbc, f.x, acc1[2]); acc1[3] = fmaf(wbc, f.y, acc1[3]);
                f = __half22float2(*(__half2*)&Bc.z); acc1[4] = fmaf(wbc, f.x, acc1[4]); acc1[5] = fmaf(wbc, f.y, acc1[5]);
                f = __half22float2(*(__half2*)&Bc.w); acc1[6] = fmaf(wbc, f.x, acc1[6]); acc1[7] = fmaf(wbc, f.y, acc1[7]);
            }
            Ac = An; Bc = Bn; wac = wan; wbc = wbn;
        }
    }
    #pragma unroll
    for (int off = 16; off; off >>= 1){
        den0 += __shfl_xor_sync(FULL, den0, off);
        den1 += __shfl_xor_sync(FULL, den1, off);
        den2 += __shfl_xor_sync(FULL, den2, off);
        den3 += __shfl_xor_sync(FULL, den3, off);
    }
    float i0 = 1.f/(den0 + 1e-16f), i1 = 1.f/(den1 + 1e-16f);
    float i2 = 1.f/(den2 + 1e-16f), i3 = 1.f/(den3 + 1e-16f);
    float sc0 = (h0==0) ? i0 : (h0==1) ? i1 : i2;
    float sc1 = (h1==2) ? i2 : i3;

    float* sp = &stage[w][0];
    *(float4*)(sp + lane*8)     = make_float4(acc0[0]*sc0, acc0[1]*sc0, acc0[2]*sc0, acc0[3]*sc0);
    *(float4*)(sp + lane*8 + 4) = make_float4(acc0[4]*sc0, acc0[5]*sc0, acc0[6]*sc0, acc0[7]*sc0);
    if (hasQ1){
        *(float4*)(sp + (32+lane)*8)     = make_float4(acc1[0]*sc1, acc1[1]*sc1, acc1[2]*sc1, acc1[3]*sc1);
        *(float4*)(sp + (32+lane)*8 + 4) = make_float4(acc1[4]*sc1, acc1[5]*sc1, acc1[6]*sc1, acc1[7]*sc1);
    }
    __syncwarp();

    float4 ag = make_float4(0,0,0,0);
    if (lane < 25){
        #pragma unroll
        for (int h = 0; h < 4; h++){
            float4 v = *(const float4*)(sp + h*104 + lane*4);
            ag.x += v.x; ag.y += v.y; ag.z += v.z; ag.w += v.w;
        }
    }

    // LayerNorm over 100 dims + ELU + residual
    float ls = (lane < 25) ? (ag.x + ag.y + ag.z + ag.w) : 0.f;
    #pragma unroll
    for (int off = 16; off; off >>= 1) ls += __shfl_xor_sync(FULL, ls, off);
    float mu = ls * 0.01f;
    float vs = 0.f;
    if (lane < 25){
        float dx = ag.x-mu, dy = ag.y-mu, dz = ag.z-mu, dw = ag.w-mu;
        vs = dx*dx + dy*dy + dz*dz + dw*dw;
    }
    #pragma unroll
    for (int off = 16; off; off >>= 1) vs += __shfl_xor_sync(FULL, vs, off);
    float rstd = rsqrtf(vs * 0.01f + 1e-5f);
    if (lane < 25){
        float4 g4   = *(const float4*)(lng + l*100 + lane*4);
        float4 b4   = *(const float4*)(lnb + l*100 + lane*4);
        float4 hold = *(const float4*)(d_h + n*100 + lane*4);
        float y;
        y = (ag.x-mu)*rstd*g4.x + b4.x; y = y > 0.f ? y : expm1f(y); hold.x += y;
        y = (ag.y-mu)*rstd*g4.y + b4.y; y = y > 0.f ? y : expm1f(y); hold.y += y;
        y = (ag.z-mu)*rstd*g4.z + b4.z; y = y > 0.f ? y : expm1f(y); hold.z += y;
        y = (ag.w-mu)*rstd*g4.w + b4.w; y = y > 0.f ? y : expm1f(y); hold.w += y;
        *(float4*)(d_h + n*100 + lane*4) = hold;
    }
}

// ---------------- pooling + MLP head ----------------
__global__ void k_pool(const int* __restrict__ batch,
                       const float* __restrict__ w1, const float* __restrict__ b1,
                       const float* __restrict__ w2, const float* __restrict__ b2,
                       float* __restrict__ out){
    __shared__ float pooled[100];
    __shared__ float hh[64];
    __shared__ int bounds[2];
    int g = blockIdx.x, t = threadIdx.x;
    if (t < 2){
        int v = g + t, lo = 0, hi = NN;
        while (lo < hi){ int m = (lo+hi) >> 1; if (batch[m] < v) lo = m+1; else hi = m; }
        bounds[t] = lo;
    }
    __syncthreads();
    int s0 = bounds[0], s1 = bounds[1];
    if (t < 100){
        float acc = 0.f;
        for (int n = s0; n < s1; n++) acc += d_h[n*100 + t];
        pooled[t] = acc / fmaxf((float)(s1 - s0), 1.f);
    }
    __syncthreads();
    if (t < 64){
        float s = b1[t];
        const float* wr = w1 + t*100;
        #pragma unroll 4
        for (int d = 0; d < 100; d++) s = fmaf(pooled[d], wr[d], s);
        hh[t] = s;
        out[128 + g*64 + t] = s;
    }
    __syncthreads();
    if (t == 0){
        float o = b2[0];
        for (int k = 0; k < 64; k++) o = fmaf(hh[k], w2[k], o);
        out[g] = o;
    }
}

// ---------------- launch ----------------
extern "C" void kernel_launch(void* const* d_in, const int* in_sizes, int n_in,
                              void* d_out, int out_size){
    (void)in_sizes; (void)n_in; (void)out_size;
    const int*   x     = (const int*)  d_in[0];
    const int*   ei    = (const int*)  d_in[1];
    const float* ea    = (const float*)d_in[2];
    const int*   batch = (const int*)  d_in[3];
    const float* emb   = (const float*)d_in[4];
    const float* W     = (const float*)d_in[5];
    const float* We    = (const float*)d_in[6];
    const float* a     = (const float*)d_in[7];
    const float* lng   = (const float*)d_in[8];
    const float* lnb   = (const float*)d_in[9];
    const float* w1    = (const float*)d_in[10];
    const float* b1    = (const float*)d_in[11];
    const float* w2    = (const float*)d_in[12];
    const float* b2    = (const float*)d_in[13];
    float* out = (float*)d_out;

    k_zero_deg<<<(NN+255)/256, 256>>>();
    k_zpad<<<(NN*16+255)/256, 256>>>();
    k_weff<<<(LL*400+255)/256, 256>>>(a, We);
    k_wt<<<(LL*40000+255)/256, 256>>>(W);
    k_es<<<(EE+63)/64, 128>>>(ea);
    k_h0<<<(NN*25+255)/256, 256>>>(x, emb);
    k_hist<<<(EP+255)/256, 256>>>(ei);
    k_scan<<<1, 1024>>>();
    k_scatter<<<(EP+255)/256, 256>>>(ei);
    for (int l = 0; l < LL; l++){
        k_gemm<<<(NN+31)/32, 256>>>(l);
        k_score<<<(NN+7)/8, 256>>>(a, l);
        k_node<<<(NN+7)/8, 256>>>(l, lng, lnb);
    }
    k_pool<<<GG, 128>>>(batch, w1, b1, w2, b2, out);
}

// round 11
// speedup vs baseline: 1.0442x; 1.0442x over previous
#include <cuda_runtime.h>
#include <cuda_fp16.h>
#include <math.h>

#define NN 30000
#define EE 480000
#define EP 510000
#define LL 6
#define GG 128
#define FULL 0xffffffffu

typedef unsigned long long ull;

// ---------------- scratch (static device globals) ----------------
__device__ __align__(16) float  d_h  [NN*100];
__device__ __align__(16) float  d_hx [NN*400];      // fp32 hx (for scores)
__device__ __align__(16) __half d_hxh[NN*416];      // fp16 hx, heads padded to 104 (for gather)
__device__ __align__(16) float  d_es [LL*(size_t)EE*4];
__device__ __align__(16) float  d_si [NN*4];
__device__ __align__(16) float  d_sj [NN*4];
__device__ __align__(16) float  d_weff[LL*400];     // [l][d][h]
__device__ __align__(16) float  d_Wt [LL*40000];    // W transposed: [l][d][j]
__device__ int d_deg[NN];
__device__ int d_rowptr[NN+1];
__device__ int d_cursor[NN];
__device__ int d_csr_src[EP];
__device__ int d_csr_eid[EP];

// ---------------- f32x2 helpers ----------------
__device__ __forceinline__ ull fma2(ull a, ull b, ull c){
    ull r; asm("fma.rn.f32x2 %0, %1, %2, %3;" : "=l"(r) : "l"(a), "l"(b), "l"(c)); return r;
}
__device__ __forceinline__ ull pack2(float lo, float hi){
    ull r; asm("mov.b64 %0, {%1, %2};" : "=l"(r) : "f"(lo), "f"(hi)); return r;
}
__device__ __forceinline__ void unpack2(ull v, float &lo, float &hi){
    asm("mov.b64 {%0, %1}, %2;" : "=f"(lo), "=f"(hi) : "l"(v));
}

// ---------------- precompute ----------------
__global__ void k_zero_deg(){
    int i = blockIdx.x*blockDim.x + threadIdx.x;
    if (i < NN) d_deg[i] = 0;
}

__global__ void k_zpad(){
    int i = blockIdx.x*blockDim.x + threadIdx.x;
    if (i >= NN*16) return;
    int n = i/16, k = i%16, h = k/4, p = k%4;
    d_hxh[(size_t)n*416 + h*104 + 100 + p] = __float2half(0.f);
}

// w_eff[l][d][h] = sum_p a[l][h][100+p] * We[l][h*100+p][d]
__global__ void k_weff(const float* __restrict__ a, const float* __restrict__ We){
    int g = blockIdx.x*blockDim.x + threadIdx.x;
    if (g >= LL*400) return;
    int l = g/400, r = g%400, h = r/100, d = r%100;
    const float* ap = a  + l*800 + h*200 + 100;
    const float* wp = We + l*40000 + (h*100)*100 + d;
    float s = 0.f;
    #pragma unroll 4
    for (int p = 0; p < 100; p++) s = fmaf(ap[p], wp[p*100], s);
    d_weff[l*400 + d*4 + h] = s;
}

// Wt[l][d][j] = W[l][j][d]
__global__ void k_wt(const float* __restrict__ W){
    int i = blockIdx.x*blockDim.x + threadIdx.x;
    if (i >= LL*40000) return;
    int l = i/40000, r = i%40000, d = r/400, j = r%400;
    d_Wt[i] = W[l*40000 + j*100 + d];
}

// es[l][e][h]: 64 edges per block, 128 threads (2 per edge, 3 layers each)
__global__ void __launch_bounds__(128) k_es(const float* __restrict__ ea){
    __shared__ __align__(16) float sw[LL*400];
    __shared__ float rows[64*101];
    int tid = threadIdx.x;
    for (int i = tid; i < LL*400; i += 128) sw[i] = d_weff[i];
    int e0 = blockIdx.x*64;
    for (int i = tid; i < 64*100; i += 128){
        int el = i/100, d = i%100;
        int e = e0 + el;
        rows[el*101 + d] = (e < EE) ? ea[(size_t)e*100 + d] : 0.f;
    }
    __syncthreads();
    int el = tid & 63, half = tid >> 6;
    int e = e0 + el;
    if (e >= EE) return;
    const float* rp = rows + el*101;
    for (int l = half*3; l < half*3 + 3; l++){
        const float4* wl = (const float4*)(sw + l*400);
        float a0=0.f, a1=0.f, a2=0.f, a3=0.f;
        #pragma unroll 4
        for (int d = 0; d < 100; d++){
            float v = rp[d];
            float4 wv = wl[d];
            a0 = fmaf(v, wv.x, a0);
            a1 = fmaf(v, wv.y, a1);
            a2 = fmaf(v, wv.z, a2);
            a3 = fmaf(v, wv.w, a3);
        }
        *(float4*)(d_es + ((size_t)l*EE + e)*4) = make_float4(a0,a1,a2,a3);
    }
}

__global__ void k_h0(const int* __restrict__ x, const float* __restrict__ emb){
    int i = blockIdx.x*blockDim.x + threadIdx.x;
    if (i >= NN*25) return;
    int n = i/25, q = i%25;
    int atom = x[n];
    *(float4*)(d_h + n*100 + q*4) = *(const float4*)(emb + atom*100 + q*4);
}

// ---------------- CSR build ----------------
__global__ void k_hist(const int* __restrict__ ei){
    int e = blockIdx.x*blockDim.x + threadIdx.x;
    if (e >= EP) return;
    int dst = (e < EE) ? ei[EE + e] : (e - EE);
    atomicAdd(&d_deg[dst], 1);
}

__global__ void k_scan(){
    __shared__ int sh[1024];
    const int CH = 30;
    int t = threadIdx.x;
    int base = t*CH;
    int s = 0;
    for (int i = 0; i < CH; i++){ int idx = base+i; if (idx < NN) s += d_deg[idx]; }
    sh[t] = s; __syncthreads();
    for (int off = 1; off < 1024; off <<= 1){
        int v = (t >= off) ? sh[t-off] : 0;
        __syncthreads();
        sh[t] += v;
        __syncthreads();
    }
    int run = sh[t] - s;
    for (int i = 0; i < CH; i++){
        int idx = base+i;
        if (idx < NN){ d_rowptr[idx] = run; d_cursor[idx] = run; run += d_deg[idx]; }
    }
    if (t == 1023) d_rowptr[NN] = sh[1023];
}

__global__ void k_scatter(const int* __restrict__ ei){
    int e = blockIdx.x*blockDim.x + threadIdx.x;
    if (e >= EP) return;
    int dst, src, eid;
    if (e < EE){ dst = ei[EE+e]; src = ei[e]; eid = e; }
    else       { dst = e - EE;   src = dst;   eid = -1; }
    int pos = atomicAdd(&d_cursor[dst], 1);
    d_csr_src[pos] = src;
    d_csr_eid[pos] = eid;
}

// ---------------- per-layer GEMM ----------------
__global__ void __launch_bounds__(256,2) k_gemm(int l){
    __shared__ float hs[100][34];
    int tid = threadIdx.x;
    int node0 = blockIdx.x*32;
    const float* Wtl = d_Wt + l*40000;
    for (int i = tid; i < 3200; i += 256){
        int nl = i/100, d = i%100;
        int n = node0 + nl;
        hs[d][nl] = (n < NN) ? d_h[n*100 + d] : 0.f;
    }
    __syncthreads();
    int j0 = tid;
    bool has1 = (tid + 256) < 400;
    ull acc0[16], acc1[16];
    #pragma unroll
    for (int k = 0; k < 16; k++){ acc0[k] = 0ull; acc1[k] = 0ull; }
    for (int d = 0; d < 100; d++){
        float a0 = __ldg(Wtl + d*400 + j0);
        float a1 = has1 ? __ldg(Wtl + d*400 + j0 + 256) : 0.f;
        ull w0 = pack2(a0, a0), w1 = pack2(a1, a1);
        const ull* hrow = (const ull*)(&hs[d][0]);
        #pragma unroll
        for (int k = 0; k < 16; k++){
            ull hv = hrow[k];
            acc0[k] = fma2(hv, w0, acc0[k]);
            acc1[k] = fma2(hv, w1, acc1[k]);
        }
    }
    int mj0 = (j0/100)*104 + j0%100;
    int mj1 = ((j0+256)/100)*104 + (j0+256)%100;
    #pragma unroll
    for (int k = 0; k < 16; k++){
        int n0 = node0 + 2*k;
        float x0, x1; unpack2(acc0[k], x0, x1);
        if (n0 < NN){
            d_hx[(size_t)n0*400 + j0] = x0;
            d_hxh[(size_t)n0*416 + mj0] = __float2half_rn(x0);
        }
        if (n0+1 < NN){
            d_hx[(size_t)(n0+1)*400 + j0] = x1;
            d_hxh[(size_t)(n0+1)*416 + mj0] = __float2half_rn(x1);
        }
        if (has1){
            float y0, y1; unpack2(acc1[k], y0, y1);
            if (n0 < NN){
                d_hx[(size_t)n0*400 + j0 + 256] = y0;
                d_hxh[(size_t)n0*416 + mj1] = __float2half_rn(y0);
            }
            if (n0+1 < NN){
                d_hx[(size_t)(n0+1)*400 + j0 + 256] = y1;
                d_hxh[(size_t)(n0+1)*416 + mj1] = __float2half_rn(y1);
            }
        }
    }
}

// ---------------- scores: warp per node ----------------
__global__ void __launch_bounds__(256) k_score(const float* __restrict__ a, int l){
    __shared__ __align__(16) float sa[800];
    int tid = threadIdx.x;
    for (int i = tid; i < 800; i += 256) sa[i] = a[l*800 + i];
    __syncthreads();
    int lane = tid & 31, w = tid >> 5;
    int n = blockIdx.x*8 + w;
    if (n >= NN) return;
    const float4* hp = (const float4*)(d_hx + (size_t)n*400);
    float s0=0,s1=0,s2=0,s3=0, t0=0,t1=0,t2=0,t3=0;
    #pragma unroll
    for (int c = 0; c < 4; c++){
        int q = lane + c*32;
        if (q >= 100) break;
        float4 x = hp[q];
        int h = q/25, p4 = q%25;
        const float4* ab = (const float4*)(sa + h*200);
        float4 A = ab[p4], J = ab[25 + p4];
        float di = x.x*A.x + x.y*A.y + x.z*A.z + x.w*A.w;
        float dj = x.x*J.x + x.y*J.y + x.z*J.z + x.w*J.w;
        if      (h == 0){ s0 += di; t0 += dj; }
        else if (h == 1){ s1 += di; t1 += dj; }
        else if (h == 2){ s2 += di; t2 += dj; }
        else            { s3 += di; t3 += dj; }
    }
    #pragma unroll
    for (int off = 16; off; off >>= 1){
        s0 += __shfl_xor_sync(FULL, s0, off); s1 += __shfl_xor_sync(FULL, s1, off);
        s2 += __shfl_xor_sync(FULL, s2, off); s3 += __shfl_xor_sync(FULL, s3, off);
        t0 += __shfl_xor_sync(FULL, t0, off); t1 += __shfl_xor_sync(FULL, t1, off);
        t2 += __shfl_xor_sync(FULL, t2, off); t3 += __shfl_xor_sync(FULL, t3, off);
    }
    if (lane < 4){
        float vi = lane==0?s0 : lane==1?s1 : lane==2?s2 : s3;
        float vj = lane==0?t0 : lane==1?t1 : lane==2?t2 : t3;
        d_si[n*4 + lane] = vi;
        d_sj[n*4 + lane] = vj;
    }
}

// ---------------- node kernel: TWO warps per node (head pair per warp) ----------------
// warp half=0 handles heads 0,1 (fp16 row uint4[0..25]); half=1 handles heads 2,3
// (uint4[26..51]). Each warp runs its own 2-head softmax; smem stage + one block
// sync combines head sums, then warp half==0 does LayerNorm+ELU+residual.
__global__ void __launch_bounds__(256) k_node(int l, const float* __restrict__ lng,
                                              const float* __restrict__ lnb){
    __shared__ float stage[4][416];
    int tid = threadIdx.x;
    int lane = tid & 31;
    int w = tid >> 5;                 // 0..7
    int pair = w >> 1, half = w & 1;  // node-in-block, head-half
    int n = blockIdx.x*4 + pair;
    bool active = n < NN;
    int rs = 0, re = 0;
    float2 si2 = make_float2(0.f, 0.f);
    if (active){
        rs = d_rowptr[n]; re = d_rowptr[n+1];
        si2 = *(const float2*)(d_si + n*4 + half*2);
    }
    int hl = (lane < 13) ? 0 : 1;     // local head of this lane's gather chunk
    bool ldOK = lane < 26;

    // pass 1: max of leaky_relu scores for this warp's two heads
    float mA = -1e30f, mB = -1e30f;
    for (int b = rs; b < re; b += 32){
        int idx = b + lane; bool ok = idx < re;
        int s   = ok ? d_csr_src[idx] : 0;
        int eid = ok ? d_csr_eid[idx] : -1;
        float2 sj = ok ? *(const float2*)(d_sj + s*4 + half*2) : make_float2(0,0);
        float2 e2 = (eid >= 0) ? *(const float2*)(d_es + ((size_t)l*EE + eid)*4 + half*2)
                               : make_float2(0,0);
        float vA = si2.x + sj.x + e2.x; vA = vA > 0.f ? vA : 0.2f*vA; if(!ok) vA = -1e30f;
        float vB = si2.y + sj.y + e2.y; vB = vB > 0.f ? vB : 0.2f*vB; if(!ok) vB = -1e30f;
        mA = fmaxf(mA, vA); mB = fmaxf(mB, vB);
    }
    #pragma unroll
    for (int off = 16; off; off >>= 1){
        mA = fmaxf(mA, __shfl_xor_sync(FULL, mA, off));
        mB = fmaxf(mB, __shfl_xor_sync(FULL, mB, off));
    }

    // pass 2: exp weights, denom, gather (1 LDG.128 per edge per warp)
    float denA = 0.f, denB = 0.f;
    float acc[8];
    #pragma unroll
    for (int k = 0; k < 8; k++) acc[k] = 0.f;
    const __half* hxh = d_hxh;
    for (int b = rs; b < re; b += 32){
        int idx = b + lane; bool ok = idx < re;
        int s   = ok ? d_csr_src[idx] : 0;
        int eid = ok ? d_csr_eid[idx] : -1;
        float2 sj = ok ? *(const float2*)(d_sj + s*4 + half*2) : make_float2(0,0);
        float2 e2 = (eid >= 0) ? *(const float2*)(d_es + ((size_t)l*EE + eid)*4 + half*2)
                               : make_float2(0,0);
        float vA = si2.x + sj.x + e2.x; vA = vA > 0.f ? vA : 0.2f*vA;
        float vB = si2.y + sj.y + e2.y; vB = vB > 0.f ? vB : 0.2f*vB;
        float eA = ok ? __expf(vA - mA) : 0.f;
        float eB = ok ? __expf(vB - mB) : 0.f;
        denA += eA; denB += eB;
        int cnt = min(32, re - b);
        for (int j = 0; j < cnt; j++){
            int   ss = __shfl_sync(FULL, s,  j);
            float wA = __shfl_sync(FULL, eA, j);
            float wB = __shfl_sync(FULL, eB, j);
            float wm = hl ? wB : wA;
            if (ldOK){
                uint4 A = __ldg((const uint4*)(hxh + (size_t)ss*416) + half*26 + lane);
                float2 f;
                f = __half22float2(*(__half2*)&A.x); acc[0] = fmaf(wm, f.x, acc[0]); acc[1] = fmaf(wm, f.y, acc[1]);
                f = __half22float2(*(__half2*)&A.y); acc[2] = fmaf(wm, f.x, acc[2]); acc[3] = fmaf(wm, f.y, acc[3]);
                f = __half22float2(*(__half2*)&A.z); acc[4] = fmaf(wm, f.x, acc[4]); acc[5] = fmaf(wm, f.y, acc[5]);
                f = __half22float2(*(__half2*)&A.w); acc[6] = fmaf(wm, f.x, acc[6]); acc[7] = fmaf(wm, f.y, acc[7]);
            }
        }
    }
    #pragma unroll
    for (int off = 16; off; off >>= 1){
        denA += __shfl_xor_sync(FULL, denA, off);
        denB += __shfl_xor_sync(FULL, denB, off);
    }
    float inv = 1.f / ((hl ? denB : denA) + 1e-16f);
    if (active && ldOK){
        float* sp = &stage[pair][half*208 + lane*8];
        *(float4*)(sp)     = make_float4(acc[0]*inv, acc[1]*inv, acc[2]*inv, acc[3]*inv);
        *(float4*)(sp + 4) = make_float4(acc[4]*inv, acc[5]*inv, acc[6]*inv, acc[7]*inv);
    }
    __syncthreads();

    if (half == 0 && active){
        float4 ag = make_float4(0,0,0,0);
        if (lane < 25){
            #pragma unroll
            for (int h = 0; h < 4; h++){
                float4 v = *(const float4*)(&stage[pair][h*104 + lane*4]);
                ag.x += v.x; ag.y += v.y; ag.z += v.z; ag.w += v.w;
            }
        }
        // LayerNorm over 100 dims + ELU + residual
        float ls = (lane < 25) ? (ag.x + ag.y + ag.z + ag.w) : 0.f;
        #pragma unroll
        for (int off = 16; off; off >>= 1) ls += __shfl_xor_sync(FULL, ls, off);
        float mu = ls * 0.01f;
        float vs = 0.f;
        if (lane < 25){
            float dx = ag.x-mu, dy = ag.y-mu, dz = ag.z-mu, dw = ag.w-mu;
            vs = dx*dx + dy*dy + dz*dz + dw*dw;
        }
        #pragma unroll
        for (int off = 16; off; off >>= 1) vs += __shfl_xor_sync(FULL, vs, off);
        float rstd = rsqrtf(vs * 0.01f + 1e-5f);
        if (lane < 25){
            float4 g4   = *(const float4*)(lng + l*100 + lane*4);
            float4 b4   = *(const float4*)(lnb + l*100 + lane*4);
            float4 hold = *(const float4*)(d_h + n*100 + lane*4);
            float y;
            y = (ag.x-mu)*rstd*g4.x + b4.x; y = y > 0.f ? y : expm1f(y); hold.x += y;
            y = (ag.y-mu)*rstd*g4.y + b4.y; y = y > 0.f ? y : expm1f(y); hold.y += y;
            y = (ag.z-mu)*rstd*g4.z + b4.z; y = y > 0.f ? y : expm1f(y); hold.z += y;
            y = (ag.w-mu)*rstd*g4.w + b4.w; y = y > 0.f ? y : expm1f(y); hold.w += y;
            *(float4*)(d_h + n*100 + lane*4) = hold;
        }
    }
}

// ---------------- pooling + MLP head ----------------
__global__ void k_pool(const int* __restrict__ batch,
                       const float* __restrict__ w1, const float* __restrict__ b1,
                       const float* __restrict__ w2, const float* __restrict__ b2,
                       float* __restrict__ out){
    __shared__ float pooled[100];
    __shared__ float hh[64];
    __shared__ int bounds[2];
    int g = blockIdx.x, t = threadIdx.x;
    if (t < 2){
        int v = g + t, lo = 0, hi = NN;
        while (lo < hi){ int m = (lo+hi) >> 1; if (batch[m] < v) lo = m+1; else hi = m; }
        bounds[t] = lo;
    }
    __syncthreads();
    int s0 = bounds[0], s1 = bounds[1];
    if (t < 100){
        float acc = 0.f;
        for (int n = s0; n < s1; n++) acc += d_h[n*100 + t];
        pooled[t] = acc / fmaxf((float)(s1 - s0), 1.f);
    }
    __syncthreads();
    if (t < 64){
        float s = b1[t];
        const float* wr = w1 + t*100;
        #pragma unroll 4
        for (int d = 0; d < 100; d++) s = fmaf(pooled[d], wr[d], s);
        hh[t] = s;
        out[128 + g*64 + t] = s;
    }
    __syncthreads();
    if (t == 0){
        float o = b2[0];
        for (int k = 0; k < 64; k++) o = fmaf(hh[k], w2[k], o);
        out[g] = o;
    }
}

// ---------------- launch ----------------
extern "C" void kernel_launch(void* const* d_in, const int* in_sizes, int n_in,
                              void* d_out, int out_size){
    (void)in_sizes; (void)n_in; (void)out_size;
    const int*   x     = (const int*)  d_in[0];
    const int*   ei    = (const int*)  d_in[1];
    const float* ea    = (const float*)d_in[2];
    const int*   batch = (const int*)  d_in[3];
    const float* emb   = (const float*)d_in[4];
    const float* W     = (const float*)d_in[5];
    const float* We    = (const float*)d_in[6];
    const float* a     = (const float*)d_in[7];
    const float* lng   = (const float*)d_in[8];
    const float* lnb   = (const float*)d_in[9];
    const float* w1    = (const float*)d_in[10];
    const float* b1    = (const float*)d_in[11];
    const float* w2    = (const float*)d_in[12];
    const float* b2    = (const float*)d_in[13];
    float* out = (float*)d_out;

    k_zero_deg<<<(NN+255)/256, 256>>>();
    k_zpad<<<(NN*16+255)/256, 256>>>();
    k_weff<<<(LL*400+255)/256, 256>>>(a, We);
    k_wt<<<(LL*40000+255)/256, 256>>>(W);
    k_es<<<(EE+63)/64, 128>>>(ea);
    k_h0<<<(NN*25+255)/256, 256>>>(x, emb);
    k_hist<<<(EP+255)/256, 256>>>(ei);
    k_scan<<<1, 1024>>>();
    k_scatter<<<(EP+255)/256, 256>>>(ei);
    for (int l = 0; l < LL; l++){
        k_gemm<<<(NN+31)/32, 256>>>(l);
        k_score<<<(NN+7)/8, 256>>>(a, l);
        k_node<<<(NN+3)/4, 256>>>(l, lng, lnb);
    }
    k_pool<<<GG, 128>>>(batch, w1, b1, w2, b2, out);
}

// round 12
// speedup vs baseline: 1.0552x; 1.0105x over previous
#include <cuda_runtime.h>
#include <cuda_fp16.h>
#include <math.h>

#define NN 30000
#define EE 480000
#define EP 510000
#define LL 6
#define GG 128
#define FULL 0xffffffffu

typedef unsigned long long ull;

// ---------------- scratch (static device globals) ----------------
__device__ __align__(16) float  d_h  [NN*100];
__device__ __align__(16) float  d_hx [NN*400];      // fp32 hx (for scores)
__device__ __align__(16) __half d_hxh[NN*416];      // fp16 hx, heads padded to 104 (for gather)
__device__ __align__(16) float  d_es [LL*(size_t)EE*4];
__device__ __align__(16) float  d_si [NN*4];
__device__ __align__(16) float  d_sj [NN*4];
__device__ __align__(16) float  d_weff[LL*400];     // [l][d][h]
__device__ __align__(16) float  d_Wt [LL*40000];    // W transposed: [l][d][j]
__device__ int d_deg[NN];
__device__ int d_rowptr[NN+1];
__device__ int d_cursor[NN];
__device__ int d_csr_src[EP];
__device__ int d_csr_eid[EP];

// ---------------- f32x2 helpers ----------------
__device__ __forceinline__ ull fma2(ull a, ull b, ull c){
    ull r; asm("fma.rn.f32x2 %0, %1, %2, %3;" : "=l"(r) : "l"(a), "l"(b), "l"(c)); return r;
}
__device__ __forceinline__ ull pack2(float lo, float hi){
    ull r; asm("mov.b64 %0, {%1, %2};" : "=l"(r) : "f"(lo), "f"(hi)); return r;
}
__device__ __forceinline__ void unpack2(ull v, float &lo, float &hi){
    asm("mov.b64 {%0, %1}, %2;" : "=f"(lo), "=f"(hi) : "l"(v));
}

// ---------------- cp.async helpers ----------------
#define CP16(dst_u32, gsrc) \
    asm volatile("cp.async.cg.shared.global [%0], [%1], 16;" :: "r"(dst_u32), "l"(gsrc) : "memory")
#define CPCOMMIT() asm volatile("cp.async.commit_group;" ::: "memory")
#define CPWAIT3()  asm volatile("cp.async.wait_group 3;"  ::: "memory")

// ---------------- precompute ----------------
__global__ void k_zero_deg(){
    int i = blockIdx.x*blockDim.x + threadIdx.x;
    if (i < NN) d_deg[i] = 0;
}

__global__ void k_zpad(){
    int i = blockIdx.x*blockDim.x + threadIdx.x;
    if (i >= NN*16) return;
    int n = i/16, k = i%16, h = k/4, p = k%4;
    d_hxh[(size_t)n*416 + h*104 + 100 + p] = __float2half(0.f);
}

// w_eff[l][d][h] = sum_p a[l][h][100+p] * We[l][h*100+p][d]
__global__ void k_weff(const float* __restrict__ a, const float* __restrict__ We){
    int g = blockIdx.x*blockDim.x + threadIdx.x;
    if (g >= LL*400) return;
    int l = g/400, r = g%400, h = r/100, d = r%100;
    const float* ap = a  + l*800 + h*200 + 100;
    const float* wp = We + l*40000 + (h*100)*100 + d;
    float s = 0.f;
    #pragma unroll 4
    for (int p = 0; p < 100; p++) s = fmaf(ap[p], wp[p*100], s);
    d_weff[l*400 + d*4 + h] = s;
}

// Wt[l][d][j] = W[l][j][d]
__global__ void k_wt(const float* __restrict__ W){
    int i = blockIdx.x*blockDim.x + threadIdx.x;
    if (i >= LL*40000) return;
    int l = i/40000, r = i%40000, d = r/400, j = r%400;
    d_Wt[i] = W[l*40000 + j*100 + d];
}

// es[l][e][h]: 64 edges per block, 128 threads (2 per edge, 3 layers each)
__global__ void __launch_bounds__(128) k_es(const float* __restrict__ ea){
    __shared__ __align__(16) float sw[LL*400];
    __shared__ float rows[64*101];
    int tid = threadIdx.x;
    for (int i = tid; i < LL*400; i += 128) sw[i] = d_weff[i];
    int e0 = blockIdx.x*64;
    for (int i = tid; i < 64*100; i += 128){
        int el = i/100, d = i%100;
        int e = e0 + el;
        rows[el*101 + d] = (e < EE) ? ea[(size_t)e*100 + d] : 0.f;
    }
    __syncthreads();
    int el = tid & 63, half = tid >> 6;
    int e = e0 + el;
    if (e >= EE) return;
    const float* rp = rows + el*101;
    for (int l = half*3; l < half*3 + 3; l++){
        const float4* wl = (const float4*)(sw + l*400);
        float a0=0.f, a1=0.f, a2=0.f, a3=0.f;
        #pragma unroll 4
        for (int d = 0; d < 100; d++){
            float v = rp[d];
            float4 wv = wl[d];
            a0 = fmaf(v, wv.x, a0);
            a1 = fmaf(v, wv.y, a1);
            a2 = fmaf(v, wv.z, a2);
            a3 = fmaf(v, wv.w, a3);
        }
        *(float4*)(d_es + ((size_t)l*EE + e)*4) = make_float4(a0,a1,a2,a3);
    }
}

__global__ void k_h0(const int* __restrict__ x, const float* __restrict__ emb){
    int i = blockIdx.x*blockDim.x + threadIdx.x;
    if (i >= NN*25) return;
    int n = i/25, q = i%25;
    int atom = x[n];
    *(float4*)(d_h + n*100 + q*4) = *(const float4*)(emb + atom*100 + q*4);
}

// ---------------- CSR build ----------------
__global__ void k_hist(const int* __restrict__ ei){
    int e = blockIdx.x*blockDim.x + threadIdx.x;
    if (e >= EP) return;
    int dst = (e < EE) ? ei[EE + e] : (e - EE);
    atomicAdd(&d_deg[dst], 1);
}

__global__ void k_scan(){
    __shared__ int sh[1024];
    const int CH = 30;
    int t = threadIdx.x;
    int base = t*CH;
    int s = 0;
    for (int i = 0; i < CH; i++){ int idx = base+i; if (idx < NN) s += d_deg[idx]; }
    sh[t] = s; __syncthreads();
    for (int off = 1; off < 1024; off <<= 1){
        int v = (t >= off) ? sh[t-off] : 0;
        __syncthreads();
        sh[t] += v;
        __syncthreads();
    }
    int run = sh[t] - s;
    for (int i = 0; i < CH; i++){
        int idx = base+i;
        if (idx < NN){ d_rowptr[idx] = run; d_cursor[idx] = run; run += d_deg[idx]; }
    }
    if (t == 1023) d_rowptr[NN] = sh[1023];
}

__global__ void k_scatter(const int* __restrict__ ei){
    int e = blockIdx.x*blockDim.x + threadIdx.x;
    if (e >= EP) return;
    int dst, src, eid;
    if (e < EE){ dst = ei[EE+e]; src = ei[e]; eid = e; }
    else       { dst = e - EE;   src = dst;   eid = -1; }
    int pos = atomicAdd(&d_cursor[dst], 1);
    d_csr_src[pos] = src;
    d_csr_eid[pos] = eid;
}

// ---------------- per-layer GEMM ----------------
__global__ void __launch_bounds__(256,2) k_gemm(int l){
    __shared__ float hs[100][34];
    int tid = threadIdx.x;
    int node0 = blockIdx.x*32;
    const float* Wtl = d_Wt + l*40000;
    for (int i = tid; i < 3200; i += 256){
        int nl = i/100, d = i%100;
        int n = node0 + nl;
        hs[d][nl] = (n < NN) ? d_h[n*100 + d] : 0.f;
    }
    __syncthreads();
    int j0 = tid;
    bool has1 = (tid + 256) < 400;
    ull acc0[16], acc1[16];
    #pragma unroll
    for (int k = 0; k < 16; k++){ acc0[k] = 0ull; acc1[k] = 0ull; }
    for (int d = 0; d < 100; d++){
        float a0 = __ldg(Wtl + d*400 + j0);
        float a1 = has1 ? __ldg(Wtl + d*400 + j0 + 256) : 0.f;
        ull w0 = pack2(a0, a0), w1 = pack2(a1, a1);
        const ull* hrow = (const ull*)(&hs[d][0]);
        #pragma unroll
        for (int k = 0; k < 16; k++){
            ull hv = hrow[k];
            acc0[k] = fma2(hv, w0, acc0[k]);
            acc1[k] = fma2(hv, w1, acc1[k]);
        }
    }
    int mj0 = (j0/100)*104 + j0%100;
    int mj1 = ((j0+256)/100)*104 + (j0+256)%100;
    #pragma unroll
    for (int k = 0; k < 16; k++){
        int n0 = node0 + 2*k;
        float x0, x1; unpack2(acc0[k], x0, x1);
        if (n0 < NN){
            d_hx[(size_t)n0*400 + j0] = x0;
            d_hxh[(size_t)n0*416 + mj0] = __float2half_rn(x0);
        }
        if (n0+1 < NN){
            d_hx[(size_t)(n0+1)*400 + j0] = x1;
            d_hxh[(size_t)(n0+1)*416 + mj0] = __float2half_rn(x1);
        }
        if (has1){
            float y0, y1; unpack2(acc1[k], y0, y1);
            if (n0 < NN){
                d_hx[(size_t)n0*400 + j0 + 256] = y0;
                d_hxh[(size_t)n0*416 + mj1] = __float2half_rn(y0);
            }
            if (n0+1 < NN){
                d_hx[(size_t)(n0+1)*400 + j0 + 256] = y1;
                d_hxh[(size_t)(n0+1)*416 + mj1] = __float2half_rn(y1);
            }
        }
    }
}

// ---------------- scores: warp per node ----------------
__global__ void __launch_bounds__(256) k_score(const float* __restrict__ a, int l){
    __shared__ __align__(16) float sa[800];
    int tid = threadIdx.x;
    for (int i = tid; i < 800; i += 256) sa[i] = a[l*800 + i];
    __syncthreads();
    int lane = tid & 31, w = tid >> 5;
    int n = blockIdx.x*8 + w;
    if (n >= NN) return;
    const float4* hp = (const float4*)(d_hx + (size_t)n*400);
    float s0=0,s1=0,s2=0,s3=0, t0=0,t1=0,t2=0,t3=0;
    #pragma unroll
    for (int c = 0; c < 4; c++){
        int q = lane + c*32;
        if (q >= 100) break;
        float4 x = hp[q];
        int h = q/25, p4 = q%25;
        const float4* ab = (const float4*)(sa + h*200);
        float4 A = ab[p4], J = ab[25 + p4];
        float di = x.x*A.x + x.y*A.y + x.z*A.z + x.w*A.w;
        float dj = x.x*J.x + x.y*J.y + x.z*J.z + x.w*J.w;
        if      (h == 0){ s0 += di; t0 += dj; }
        else if (h == 1){ s1 += di; t1 += dj; }
        else if (h == 2){ s2 += di; t2 += dj; }
        else            { s3 += di; t3 += dj; }
    }
    #pragma unroll
    for (int off = 16; off; off >>= 1){
        s0 += __shfl_xor_sync(FULL, s0, off); s1 += __shfl_xor_sync(FULL, s1, off);
        s2 += __shfl_xor_sync(FULL, s2, off); s3 += __shfl_xor_sync(FULL, s3, off);
        t0 += __shfl_xor_sync(FULL, t0, off); t1 += __shfl_xor_sync(FULL, t1, off);
        t2 += __shfl_xor_sync(FULL, t2, off); t3 += __shfl_xor_sync(FULL, t3, off);
    }
    if (lane < 4){
        float vi = lane==0?s0 : lane==1?s1 : lane==2?s2 : s3;
        float vj = lane==0?t0 : lane==1?t1 : lane==2?t2 : t3;
        d_si[n*4 + lane] = vi;
        d_sj[n*4 + lane] = vj;
    }
}

// ---------------- node kernel: warp per node, cp.async smem-ring gather ----------------
__global__ void __launch_bounds__(256) k_node(int l, const float* __restrict__ lng,
                                              const float* __restrict__ lnb){
    __shared__ float stage[8][416];
    __shared__ __align__(16) char ring[8][4][832];
    int lane = threadIdx.x & 31, w = threadIdx.x >> 5;
    int n = blockIdx.x*8 + w;
    if (n >= NN) return;
    int rs = d_rowptr[n], re = d_rowptr[n+1];
    float4 si = *(const float4*)(d_si + n*4);
    int h0 = lane/13;                 // 0..2
    int h1 = (lane+32)/13;            // 2..3
    bool hasQ1 = lane < 20;
    unsigned rbase = (unsigned)__cvta_generic_to_shared(&ring[w][0][0]);

    // pass 1: per-head max of leaky_relu scores
    float m0=-1e30f, m1=-1e30f, m2=-1e30f, m3=-1e30f;
    for (int b = rs; b < re; b += 32){
        int idx = b + lane; bool ok = idx < re;
        int s   = ok ? d_csr_src[idx] : 0;
        int eid = ok ? d_csr_eid[idx] : -1;
        float4 sj = ok ? *(const float4*)(d_sj + s*4) : make_float4(0,0,0,0);
        float4 e4 = (eid >= 0) ? *(const float4*)(d_es + ((size_t)l*EE + eid)*4)
                               : make_float4(0,0,0,0);
        float v0 = si.x + sj.x + e4.x; v0 = v0 > 0.f ? v0 : 0.2f*v0; if(!ok) v0 = -1e30f;
        float v1 = si.y + sj.y + e4.y; v1 = v1 > 0.f ? v1 : 0.2f*v1; if(!ok) v1 = -1e30f;
        float v2 = si.z + sj.z + e4.z; v2 = v2 > 0.f ? v2 : 0.2f*v2; if(!ok) v2 = -1e30f;
        float v3 = si.w + sj.w + e4.w; v3 = v3 > 0.f ? v3 : 0.2f*v3; if(!ok) v3 = -1e30f;
        m0 = fmaxf(m0, v0); m1 = fmaxf(m1, v1); m2 = fmaxf(m2, v2); m3 = fmaxf(m3, v3);
    }
    #pragma unroll
    for (int off = 16; off; off >>= 1){
        m0 = fmaxf(m0, __shfl_xor_sync(FULL, m0, off));
        m1 = fmaxf(m1, __shfl_xor_sync(FULL, m1, off));
        m2 = fmaxf(m2, __shfl_xor_sync(FULL, m2, off));
        m3 = fmaxf(m3, __shfl_xor_sync(FULL, m3, off));
    }

    // pass 2: exp weights, denom, cp.async-pipelined gather
    float den0=0.f, den1=0.f, den2=0.f, den3=0.f;
    float acc0[8], acc1[8];
    #pragma unroll
    for (int k = 0; k < 8; k++){ acc0[k] = 0.f; acc1[k] = 0.f; }
    const char* hxb = (const char*)d_hxh;
    for (int b = rs; b < re; b += 32){
        int idx = b + lane; bool ok = idx < re;
        int s   = ok ? d_csr_src[idx] : 0;
        int eid = ok ? d_csr_eid[idx] : -1;
        float4 sj = ok ? *(const float4*)(d_sj + s*4) : make_float4(0,0,0,0);
        float4 e4 = (eid >= 0) ? *(const float4*)(d_es + ((size_t)l*EE + eid)*4)
                               : make_float4(0,0,0,0);
        float v0 = si.x + sj.x + e4.x; v0 = v0 > 0.f ? v0 : 0.2f*v0;
        float v1 = si.y + sj.y + e4.y; v1 = v1 > 0.f ? v1 : 0.2f*v1;
        float v2 = si.z + sj.z + e4.z; v2 = v2 > 0.f ? v2 : 0.2f*v2;
        float v3 = si.w + sj.w + e4.w; v3 = v3 > 0.f ? v3 : 0.2f*v3;
        float e0 = ok ? __expf(v0 - m0) : 0.f;
        float e1 = ok ? __expf(v1 - m1) : 0.f;
        float e2 = ok ? __expf(v2 - m2) : 0.f;
        float e3 = ok ? __expf(v3 - m3) : 0.f;
        den0 += e0; den1 += e1; den2 += e2; den3 += e3;
        int cnt = min(32, re - b);

        // prologue: issue copies for edges 0..2 (one commit per slot, always)
        #pragma unroll
        for (int q = 0; q < 3; q++){
            if (q < cnt){
                int ssq = __shfl_sync(FULL, s, q);
                const char* g = hxb + (size_t)ssq*832;
                unsigned dst = rbase + q*832;
                CP16(dst + lane*16, g + lane*16);
                if (hasQ1) CP16(dst + (32+lane)*16, g + (32+lane)*16);
            }
            CPCOMMIT();
        }
        for (int j = 0; j < cnt; j++){
            int jp = j + 3;
            if (jp < cnt){
                int ssp = __shfl_sync(FULL, s, jp);
                const char* g = hxb + (size_t)ssp*832;
                unsigned dst = rbase + (jp & 3)*832;
                CP16(dst + lane*16, g + lane*16);
                if (hasQ1) CP16(dst + (32+lane)*16, g + (32+lane)*16);
            }
            CPCOMMIT();
            CPWAIT3();                       // edge j's group is complete
            float w0 = __shfl_sync(FULL, e0, j);
            float w1 = __shfl_sync(FULL, e1, j);
            float w2 = __shfl_sync(FULL, e2, j);
            float w3 = __shfl_sync(FULL, e3, j);
            float wa = (h0==0) ? w0 : (h0==1) ? w1 : w2;
            float wb = (h1==2) ? w2 : w3;
            const uint4* sp4 = (const uint4*)(&ring[w][j & 3][0]);
            uint4 A = sp4[lane];
            float2 f;
            f = __half22float2(*(__half2*)&A.x); acc0[0] = fmaf(wa, f.x, acc0[0]); acc0[1] = fmaf(wa, f.y, acc0[1]);
            f = __half22float2(*(__half2*)&A.y); acc0[2] = fmaf(wa, f.x, acc0[2]); acc0[3] = fmaf(wa, f.y, acc0[3]);
            f = __half22float2(*(__half2*)&A.z); acc0[4] = fmaf(wa, f.x, acc0[4]); acc0[5] = fmaf(wa, f.y, acc0[5]);
            f = __half22float2(*(__half2*)&A.w); acc0[6] = fmaf(wa, f.x, acc0[6]); acc0[7] = fmaf(wa, f.y, acc0[7]);
            if (hasQ1){
                uint4 B = sp4[32 + lane];
                f = __half22float2(*(__half2*)&B.x); acc1[0] = fmaf(wb, f.x, acc1[0]); acc1[1] = fmaf(wb, f.y, acc1[1]);
                f = __half22float2(*(__half2*)&B.y); acc1[2] = fmaf(wb, f.x, acc1[2]); acc1[3] = fmaf(wb, f.y, acc1[3]);
                f = __half22float2(*(__half2*)&B.z); acc1[4] = fmaf(wb, f.x, acc1[4]); acc1[5] = fmaf(wb, f.y, acc1[5]);
                f = __half22float2(*(__half2*)&B.w); acc1[6] = fmaf(wb, f.x, acc1[6]); acc1[7] = fmaf(wb, f.y, acc1[7]);
            }
        }
    }
    #pragma unroll
    for (int off = 16; off; off >>= 1){
        den0 += __shfl_xor_sync(FULL, den0, off);
        den1 += __shfl_xor_sync(FULL, den1, off);
        den2 += __shfl_xor_sync(FULL, den2, off);
        den3 += __shfl_xor_sync(FULL, den3, off);
    }
    float i0 = 1.f/(den0 + 1e-16f), i1 = 1.f/(den1 + 1e-16f);
    float i2 = 1.f/(den2 + 1e-16f), i3 = 1.f/(den3 + 1e-16f);
    float sc0 = (h0==0) ? i0 : (h0==1) ? i1 : i2;
    float sc1 = (h1==2) ? i2 : i3;

    float* sp = &stage[w][0];
    *(float4*)(sp + lane*8)     = make_float4(acc0[0]*sc0, acc0[1]*sc0, acc0[2]*sc0, acc0[3]*sc0);
    *(float4*)(sp + lane*8 + 4) = make_float4(acc0[4]*sc0, acc0[5]*sc0, acc0[6]*sc0, acc0[7]*sc0);
    if (hasQ1){
        *(float4*)(sp + (32+lane)*8)     = make_float4(acc1[0]*sc1, acc1[1]*sc1, acc1[2]*sc1, acc1[3]*sc1);
        *(float4*)(sp + (32+lane)*8 + 4) = make_float4(acc1[4]*sc1, acc1[5]*sc1, acc1[6]*sc1, acc1[7]*sc1);
    }
    __syncwarp();

    float4 ag = make_float4(0,0,0,0);
    if (lane < 25){
        #pragma unroll
        for (int h = 0; h < 4; h++){
            float4 v = *(const float4*)(sp + h*104 + lane*4);
            ag.x += v.x; ag.y += v.y; ag.z += v.z; ag.w += v.w;
        }
    }

    // LayerNorm over 100 dims + ELU + residual
    float ls = (lane < 25) ? (ag.x + ag.y + ag.z + ag.w) : 0.f;
    #pragma unroll
    for (int off = 16; off; off >>= 1) ls += __shfl_xor_sync(FULL, ls, off);
    float mu = ls * 0.01f;
    float vs = 0.f;
    if (lane < 25){
        float dx = ag.x-mu, dy = ag.y-mu, dz = ag.z-mu, dw = ag.w-mu;
        vs = dx*dx + dy*dy + dz*dz + dw*dw;
    }
    #pragma unroll
    for (int off = 16; off; off >>= 1) vs += __shfl_xor_sync(FULL, vs, off);
    float rstd = rsqrtf(vs * 0.01f + 1e-5f);
    if (lane < 25){
        float4 g4   = *(const float4*)(lng + l*100 + lane*4);
        float4 b4   = *(const float4*)(lnb + l*100 + lane*4);
        float4 hold = *(const float4*)(d_h + n*100 + lane*4);
        float y;
        y = (ag.x-mu)*rstd*g4.x + b4.x; y = y > 0.f ? y : expm1f(y); hold.x += y;
        y = (ag.y-mu)*rstd*g4.y + b4.y; y = y > 0.f ? y : expm1f(y); hold.y += y;
        y = (ag.z-mu)*rstd*g4.z + b4.z; y = y > 0.f ? y : expm1f(y); hold.z += y;
        y = (ag.w-mu)*rstd*g4.w + b4.w; y = y > 0.f ? y : expm1f(y); hold.w += y;
        *(float4*)(d_h + n*100 + lane*4) = hold;
    }
}

// ---------------- pooling + MLP head ----------------
__global__ void k_pool(const int* __restrict__ batch,
                       const float* __restrict__ w1, const float* __restrict__ b1,
                       const float* __restrict__ w2, const float* __restrict__ b2,
                       float* __restrict__ out){
    __shared__ float pooled[100];
    __shared__ float hh[64];
    __shared__ int bounds[2];
    int g = blockIdx.x, t = threadIdx.x;
    if (t < 2){
        int v = g + t, lo = 0, hi = NN;
        while (lo < hi){ int m = (lo+hi) >> 1; if (batch[m] < v) lo = m+1; else hi = m; }
        bounds[t] = lo;
    }
    __syncthreads();
    int s0 = bounds[0], s1 = bounds[1];
    if (t < 100){
        float acc = 0.f;
        for (int n = s0; n < s1; n++) acc += d_h[n*100 + t];
        pooled[t] = acc / fmaxf((float)(s1 - s0), 1.f);
    }
    __syncthreads();
    if (t < 64){
        float s = b1[t];
        const float* wr = w1 + t*100;
        #pragma unroll 4
        for (int d = 0; d < 100; d++) s = fmaf(pooled[d], wr[d], s);
        hh[t] = s;
        out[128 + g*64 + t] = s;
    }
    __syncthreads();
    if (t == 0){
        float o = b2[0];
        for (int k = 0; k < 64; k++) o = fmaf(hh[k], w2[k], o);
        out[g] = o;
    }
}

// ---------------- launch ----------------
extern "C" void kernel_launch(void* const* d_in, const int* in_sizes, int n_in,
                              void* d_out, int out_size){
    (void)in_sizes; (void)n_in; (void)out_size;
    const int*   x     = (const int*)  d_in[0];
    const int*   ei    = (const int*)  d_in[1];
    const float* ea    = (const float*)d_in[2];
    const int*   batch = (const int*)  d_in[3];
    const float* emb   = (const float*)d_in[4];
    const float* W     = (const float*)d_in[5];
    const float* We    = (const float*)d_in[6];
    const float* a     = (const float*)d_in[7];
    const float* lng   = (const float*)d_in[8];
    const float* lnb   = (const float*)d_in[9];
    const float* w1    = (const float*)d_in[10];
    const float* b1    = (const float*)d_in[11];
    const float* w2    = (const float*)d_in[12];
    const float* b2    = (const float*)d_in[13];
    float* out = (float*)d_out;

    k_zero_deg<<<(NN+255)/256, 256>>>();
    k_zpad<<<(NN*16+255)/256, 256>>>();
    k_weff<<<(LL*400+255)/256, 256>>>(a, We);
    k_wt<<<(LL*40000+255)/256, 256>>>(W);
    k_es<<<(EE+63)/64, 128>>>(ea);
    k_h0<<<(NN*25+255)/256, 256>>>(x, emb);
    k_hist<<<(EP+255)/256, 256>>>(ei);
    k_scan<<<1, 1024>>>();
    k_scatter<<<(EP+255)/256, 256>>>(ei);
    for (int l = 0; l < LL; l++){
        k_gemm<<<(NN+31)/32, 256>>>(l);
        k_score<<<(NN+7)/8, 256>>>(a, l);
        k_node<<<(NN+7)/8, 256>>>(l, lng, lnb);
    }
    k_pool<<<GG, 128>>>(batch, w1, b1, w2, b2, out);
}